// round 7
// baseline (speedup 1.0000x reference)
#include <cuda_runtime.h>
#include <cuda_bf16.h>
#include <cstdint>

// Problem constants (fixed shapes)
#define BB 8192
#define DD 256
#define KK 64

// ---------------- scratch (static device arrays; no allocation) ----------------
__device__ __nv_bfloat16 g_Xbf[BB * DD];          // 4 MB
__device__ __nv_bfloat16 g_Sbf[KK * DD * DD];     // 8.4 MB
__device__ float         g_logits[BB * KK];       // 2 MB
__device__ float         g_contrib[KK * BB];      // 2 MB

// ---------------- helpers ----------------
__device__ __forceinline__ uint32_t smem_to_u32(const void* p) {
    uint32_t a;
    asm("{ .reg .u64 t; cvta.to.shared.u64 t, %1; cvt.u32.u64 %0, t; }" : "=r"(a) : "l"(p));
    return a;
}

__device__ __forceinline__ void cp_async16(uint32_t dst, const void* src) {
    asm volatile("cp.async.cg.shared.global [%0], [%1], 16;" :: "r"(dst), "l"(src));
}
#define CP_COMMIT() asm volatile("cp.async.commit_group;" ::: "memory")
#define CP_WAIT(n)  asm volatile("cp.async.wait_group %0;" :: "n"(n) : "memory")

__device__ __forceinline__ void ldsm_x4(uint32_t& r0, uint32_t& r1, uint32_t& r2, uint32_t& r3,
                                        uint32_t addr) {
    asm volatile("ldmatrix.sync.aligned.m8n8.x4.shared.b16 {%0,%1,%2,%3}, [%4];"
                 : "=r"(r0), "=r"(r1), "=r"(r2), "=r"(r3) : "r"(addr));
}

__device__ __forceinline__ void mma_bf16(float* d, const uint32_t* a, uint32_t b0, uint32_t b1) {
    asm volatile(
        "mma.sync.aligned.m16n8k16.row.col.f32.bf16.bf16.f32 "
        "{%0,%1,%2,%3}, {%4,%5,%6,%7}, {%8,%9}, {%0,%1,%2,%3};"
        : "+f"(d[0]), "+f"(d[1]), "+f"(d[2]), "+f"(d[3])
        : "r"(a[0]), "r"(a[1]), "r"(a[2]), "r"(a[3]), "r"(b0), "r"(b1));
}

// ---------------- kernels 1a/1b: fp32 -> bf16 converts ----------------
#define NX4 (BB * DD / 4)
#define NS4 (KK * DD * DD / 4)
__global__ void convX_kernel(const float4* __restrict__ src) {
    int i = blockIdx.x * blockDim.x + threadIdx.x;
    if (i < NX4) {
        float4 v = src[i];
        __nv_bfloat162* dst = reinterpret_cast<__nv_bfloat162*>(g_Xbf);
        dst[2 * i]     = __floats2bfloat162_rn(v.x, v.y);
        dst[2 * i + 1] = __floats2bfloat162_rn(v.z, v.w);
    }
}
__global__ void convS_kernel(const float4* __restrict__ src) {
    int i = blockIdx.x * blockDim.x + threadIdx.x;
    if (i < NS4) {
        float4 v = src[i];
        __nv_bfloat162* dst = reinterpret_cast<__nv_bfloat162*>(g_Sbf);
        dst[2 * i]     = __floats2bfloat162_rn(v.x, v.y);
        dst[2 * i + 1] = __floats2bfloat162_rn(v.z, v.w);
    }
}

// ---------------- kernel 2: logits = X @ mu (fp32, exact) ----------------
#define LOGITS_SMEM ((128 * 257 + 256 * 64) * 4)
__global__ void logits_kernel(const float* __restrict__ X, const float* __restrict__ mu) {
    extern __shared__ float sm[];
    float* xs  = sm;                // [128][257] padded
    float* mus = sm + 128 * 257;    // [256][64]
    int t = threadIdx.x;
    int b0 = blockIdx.x * 128;

    const float4* xg = reinterpret_cast<const float4*>(X + (size_t)b0 * DD);
    #pragma unroll
    for (int j = 0; j < 32; j++) {
        int i = t + j * 256;
        float4 v = xg[i];
        int r = i >> 6, c = (i & 63) << 2;
        float* p = xs + r * 257 + c;
        p[0] = v.x; p[1] = v.y; p[2] = v.z; p[3] = v.w;
    }
    const float4* mg = reinterpret_cast<const float4*>(mu);
    float4* ms4 = reinterpret_cast<float4*>(mus);
    #pragma unroll
    for (int j = 0; j < 16; j++) ms4[t + j * 256] = mg[t + j * 256];
    __syncthreads();

    int r = t & 127;
    int kh = (t >> 7) * 32;
    float acc[32];
    #pragma unroll
    for (int kk = 0; kk < 32; kk++) acc[kk] = 0.f;
    const float* xr = xs + r * 257;
    for (int d = 0; d < DD; d++) {
        float xv = xr[d];
        const float* mrow = mus + d * 64 + kh;
        #pragma unroll
        for (int kk = 0; kk < 32; kk++) acc[kk] = fmaf(xv, mrow[kk], acc[kk]);
    }
    float* og = g_logits + (size_t)(b0 + r) * KK + kh;
    #pragma unroll
    for (int kk = 0; kk < 32; kk++) og[kk] = acc[kk];
}

// ---------------- kernel 3: main GEMM + loss ----------------
// grid (32 b-tiles, 64 k), 256 threads (8 warps, m32 each), 2 CTAs/SM.
// A fragments: half of d (128) in regs (64 regs), two d-passes.
// B (Sigma_k): chunks of 64 e-rows x 128 d = 16 KB, 3-deep cp.async ring (48 KB).
// Chunk c = h*4+q: h = d-half, q = e-quarter. 8 chunks total, Sigma read once.
#define CHUNK_B 16384
#define GEMM_SMEM (3 * CHUNK_B)

__device__ __forceinline__ void issue_chunk(uint32_t sb, int tid, int k, int c) {
    int h = c >> 2, q = c & 3;
    const char* src = reinterpret_cast<const char*>(g_Sbf)
                    + (size_t)k * 131072 + (size_t)q * 64 * 512 + (size_t)h * 256;
    uint32_t base = sb + (uint32_t)(c % 3) * (uint32_t)CHUNK_B;
    #pragma unroll
    for (int j = 0; j < 4; j++) {
        int i = tid + j * 256;
        int row = i >> 4;                           // 0..63 e-rows
        uint32_t colb = (uint32_t)(i & 15) * 16u;   // 0..240 within 256B row
        uint32_t dst = base + (uint32_t)row * 256u + (colb & 0xFFFFFF80u)
                     + ((colb & 127u) ^ (((uint32_t)row & 7u) << 4));
        cp_async16(dst, src + (size_t)row * 512 + colb);
    }
}

__global__ void __launch_bounds__(256, 2)
gemm_loss_kernel(const int* __restrict__ y) {
    extern __shared__ char smem[];
    uint32_t sb = smem_to_u32(smem);
    int tid = threadIdx.x, wid = tid >> 5, lid = tid & 31;
    int bt = blockIdx.x, k = blockIdx.y;
    int Rw = bt * 256 + wid * 32;           // warp's 32 batch rows
    int gq = lid >> 2, cq = lid & 3;
    int lrow = lid & 15;
    uint32_t lcb16 = (uint32_t)(lid >> 4) * 16u;

    // prologue: start the ring (chunks 0,1,2 -> buffers 0,1,2)
    issue_chunk(sb, tid, k, 0); CP_COMMIT();
    issue_chunk(sb, tid, k, 1); CP_COMMIT();
    issue_chunk(sb, tid, k, 2); CP_COMMIT();

    uint32_t afr[2][8][4];                  // A frags for current d-half (64 regs)
    float rs[2][2] = {{0.f, 0.f}, {0.f, 0.f}};

    #pragma unroll 1
    for (int c = 0; c < 8; c++) {
        if ((c & 3) == 0) {                 // (re)load A fragments for half h = c>>2
            int h = c >> 2;
            #pragma unroll
            for (int mt = 0; mt < 2; mt++) {
                int r0 = Rw + mt * 16 + gq;
                const uint32_t* p0 = reinterpret_cast<const uint32_t*>(g_Xbf + (size_t)r0 * 256) + h * 64;
                const uint32_t* p1 = reinterpret_cast<const uint32_t*>(g_Xbf + (size_t)(r0 + 8) * 256) + h * 64;
                #pragma unroll
                for (int s = 0; s < 8; s++) {
                    afr[mt][s][0] = p0[8 * s + cq];
                    afr[mt][s][1] = p1[8 * s + cq];
                    afr[mt][s][2] = p0[8 * s + cq + 4];
                    afr[mt][s][3] = p1[8 * s + cq + 4];
                }
            }
        }
        // exact wait for chunk c (3 buffers, consume-then-issue => <=2 groups newer)
        if      (c <= 5) CP_WAIT(2);
        else if (c == 6) CP_WAIT(1);
        else             CP_WAIT(0);
        __syncthreads();

        uint32_t qbase = sb + (uint32_t)(c % 3) * (uint32_t)CHUNK_B;
        int q = c & 3;

        #pragma unroll
        for (int t = 0; t < 4; t++) {       // 4 n16-tiles in this e-quarter
            float acc[2][2][4];
            #pragma unroll
            for (int mt = 0; mt < 2; mt++)
                #pragma unroll
                for (int n = 0; n < 2; n++)
                    #pragma unroll
                    for (int f = 0; f < 4; f++) acc[mt][n][f] = 0.f;

            uint32_t rowa = (uint32_t)(t * 16 + lrow);
            uint32_t rbase = qbase + rowa * 256u;
            uint32_t rxor = (rowa & 7u) << 4;
            #pragma unroll
            for (int s = 0; s < 8; s++) {
                uint32_t colb = 32u * (uint32_t)s + lcb16;
                uint32_t addr = rbase + (colb & 0xFFFFFF80u) + ((colb & 127u) ^ rxor);
                uint32_t b0, b1, b2, b3;
                ldsm_x4(b0, b1, b2, b3, addr);
                mma_bf16(acc[0][0], afr[0][s], b0, b2);
                mma_bf16(acc[1][0], afr[1][s], b0, b2);
                mma_bf16(acc[0][1], afr[0][s], b1, b3);
                mma_bf16(acc[1][1], afr[1][s], b1, b3);
            }
            // contract this n16 tile into scalars (x weights, L1-hot)
            int ebase = q * 64 + t * 16;
            #pragma unroll
            for (int mt = 0; mt < 2; mt++) {
                int r0 = Rw + mt * 16 + gq;
                const uint32_t* q0 = reinterpret_cast<const uint32_t*>(g_Xbf + (size_t)r0 * 256 + ebase);
                const uint32_t* q1 = reinterpret_cast<const uint32_t*>(g_Xbf + (size_t)(r0 + 8) * 256 + ebase);
                uint32_t w0 = q0[cq], w1 = q0[cq + 4], w2 = q1[cq], w3 = q1[cq + 4];
                float2 v;
                v = __bfloat1622float2(*reinterpret_cast<__nv_bfloat162*>(&w0));
                rs[mt][0] = fmaf(acc[mt][0][0], v.x, fmaf(acc[mt][0][1], v.y, rs[mt][0]));
                v = __bfloat1622float2(*reinterpret_cast<__nv_bfloat162*>(&w1));
                rs[mt][0] = fmaf(acc[mt][1][0], v.x, fmaf(acc[mt][1][1], v.y, rs[mt][0]));
                v = __bfloat1622float2(*reinterpret_cast<__nv_bfloat162*>(&w2));
                rs[mt][1] = fmaf(acc[mt][0][2], v.x, fmaf(acc[mt][0][3], v.y, rs[mt][1]));
                v = __bfloat1622float2(*reinterpret_cast<__nv_bfloat162*>(&w3));
                rs[mt][1] = fmaf(acc[mt][1][2], v.x, fmaf(acc[mt][1][3], v.y, rs[mt][1]));
            }
        }
        __syncthreads();                    // buffer free for re-fill
        if (c + 3 < 8) { issue_chunk(sb, tid, k, c + 3); CP_COMMIT(); }
    }

    // ---- loss epilogue ----
    #pragma unroll
    for (int mt = 0; mt < 2; mt++)
        #pragma unroll
        for (int h = 0; h < 2; h++) {
            float v = rs[mt][h];
            v += __shfl_xor_sync(0xFFFFFFFF, v, 1);
            v += __shfl_xor_sync(0xFFFFFFFF, v, 2);
            rs[mt][h] = v;
        }
    if (cq == 0) {
        #pragma unroll
        for (int mt = 0; mt < 2; mt++)
            #pragma unroll
            for (int h = 0; h < 2; h++) {
                int b = Rw + mt * 16 + gq + h * 8;
                float l = g_logits[(size_t)b * KK + k];
                int yv = y[b];
                float psi = sqrtf(fmaxf(rs[mt][h], 0.f) + l * l);
                float bk  = (k <= yv) ? 1.f : 0.f;
                float kap = ((k == yv) ? 1.f : 0.f) - 0.5f * bk;
                float sp  = psi + log1pf(__expf(-psi));   // softplus(psi), psi>=0
                g_contrib[(size_t)k * BB + b] = l * kap + bk * (0.5f * psi - sp);
            }
    }
}

// ---------------- kernel 4: deterministic reduce over k ----------------
__global__ void reduce_kernel(float* __restrict__ out) {
    int b = blockIdx.x * blockDim.x + threadIdx.x;
    if (b < BB) {
        float s = 0.f;
        #pragma unroll 8
        for (int kk = 0; kk < KK; kk++) s += g_contrib[(size_t)kk * BB + b];
        out[b] = -s;
    }
}

// ---------------- launch ----------------
extern "C" void kernel_launch(void* const* d_in, const int* in_sizes, int n_in,
                              void* d_out, int out_size) {
    (void)in_sizes; (void)n_in; (void)out_size;
    const float* features = (const float*)d_in[0];
    const int*   y        = (const int*)d_in[1];
    const float* mu       = (const float*)d_in[2];
    const float* Sigma    = (const float*)d_in[3];
    float* out = (float*)d_out;

    cudaFuncSetAttribute(logits_kernel,    cudaFuncAttributeMaxDynamicSharedMemorySize, LOGITS_SMEM);
    cudaFuncSetAttribute(gemm_loss_kernel, cudaFuncAttributeMaxDynamicSharedMemorySize, GEMM_SMEM);

    convX_kernel<<<(NX4 + 255) / 256, 256>>>(reinterpret_cast<const float4*>(features));
    convS_kernel<<<(NS4 + 255) / 256, 256>>>(reinterpret_cast<const float4*>(Sigma));
    logits_kernel<<<BB / 128, 256, LOGITS_SMEM>>>(features, mu);
    dim3 grid(BB / 256, KK);
    gemm_loss_kernel<<<grid, 256, GEMM_SMEM>>>(y);
    reduce_kernel<<<BB / 256, 256>>>(out);
}